// round 2
// baseline (speedup 1.0000x reference)
#include <cuda_runtime.h>
#include <cstdint>

// Problem constants (fixed shapes from reference setup_inputs)
#define C_   256
#define H_   256
#define W_   256
#define HW_  (H_ * W_)
#define CHW_ (C_ * H_ * W_)
#define HWC_ (H_ * W_ * C_)
#define B_   2
#define NROI 1024          // B * N = 2 * 512
#define OUTH 7
#define OUTW 7
#define NBINS 49
#define OUT_PER_ROI (C_ * NBINS)   // 12544

// 128 MB NHWC scratch (device global — allocation-free per harness rules)
__device__ float g_xt[(size_t)B_ * HWC_];

// ---------------------------------------------------------------------------
// Kernel A: NCHW -> NHWC transpose. Per batch: 2D transpose [C=256][P=65536].
// 32x32 tiles via smem, fully coalesced reads and writes.
// ---------------------------------------------------------------------------
__global__ void transpose_nchw_nhwc(const float* __restrict__ x) {
    __shared__ float tile[32][33];
    const int b  = blockIdx.z;
    const int p0 = blockIdx.x * 32;   // position within H*W
    const int c0 = blockIdx.y * 32;   // channel
    const float* src = x    + (size_t)b * CHW_;
    float*       dst = g_xt + (size_t)b * HWC_;
    const int tx = threadIdx.x, ty = threadIdx.y;
#pragma unroll
    for (int j = 0; j < 32; j += 8)
        tile[ty + j][tx] = __ldg(src + (size_t)(c0 + ty + j) * HW_ + p0 + tx);
    __syncthreads();
#pragma unroll
    for (int j = 0; j < 32; j += 8)
        dst[(size_t)(p0 + ty + j) * C_ + (c0 + tx)] = tile[tx][ty + j];
}

// ---------------------------------------------------------------------------
// Kernel B: rotated ROI pool. One block per ROI, 256 threads = 256 channels.
// Geometry (threads 0..48) replicates the reference's fp32 arithmetic exactly:
//  - cosf/sinf (libdevice, same as XLA:GPU)
//  - explicit *_rn intrinsics, left-associated like the jnp expressions
//  - rintf == jnp.round (round-half-even)
// ---------------------------------------------------------------------------
__global__ void rroi_pool_kernel(const float* __restrict__ boxes,
                                 float* __restrict__ out) {
    extern __shared__ char smem_raw[];
    int*   soff = (int*)smem_raw;                         // [49][4]
    float* swt  = (float*)(smem_raw + NBINS * 4 * 4);     // [49][4]
    float* sout = (float*)(smem_raw + NBINS * 4 * 4 * 2); // [12544]

    const int r   = blockIdx.x;
    const int tid = threadIdx.x;

    if (tid < NBINS) {
        const float* bx = boxes + r * 5;
        const int b = r >> 9;   // batch id (N = 512 rois per batch)

        const float cx  = __fmul_rn(bx[0], 0.25f);
        const float cy  = __fmul_rn(bx[1], 0.25f);
        const float w   = __fmul_rn(bx[2], 0.25f);
        const float h   = __fmul_rn(bx[3], 0.25f);
        const float ang = __fmul_rn(bx[4], 0.017453292519943295f);

        const float Sx = __fdiv_rn(w, 7.0f);
        const float Sy = __fdiv_rn(h, 7.0f);
        const float ca = cosf(ang);
        const float sa = sinf(ang);

        const float M00 = __fmul_rn(ca, Sx);
        const float M01 = __fmul_rn(sa, Sy);
        const float M02 = __fadd_rn(
            __fadd_rn(__fmul_rn(M00, -3.5f), __fmul_rn(M01, -3.5f)), cx);
        const float M10 = __fmul_rn(-sa, Sx);
        const float M11 = __fmul_rn(ca, Sy);
        const float M12 = __fadd_rn(
            __fadd_rn(__fmul_rn(M10, -3.5f), __fmul_rn(M11, -3.5f)), cy);

        const int ph = tid / OUTW;
        const int pw = tid % OUTW;
        const float phf = (float)ph, pwf = (float)pw;

        float minX =  1e30f, maxX = -1e30f, minY = 1e30f, maxY = -1e30f;
#pragma unroll
        for (int i = 0; i < 2; i++) {
#pragma unroll
            for (int j = 0; j < 2; j++) {
                const float pc = pwf + (float)i;   // pw + off0
                const float qc = phf + (float)j;   // ph + off1
                const float X = __fadd_rn(
                    __fadd_rn(__fmul_rn(M00, pc), __fmul_rn(M01, qc)), M02);
                const float Y = __fadd_rn(
                    __fadd_rn(__fmul_rn(M10, pc), __fmul_rn(M11, qc)), M12);
                minX = fminf(minX, X); maxX = fmaxf(maxX, X);
                minY = fminf(minY, Y); maxY = fmaxf(maxY, Y);
            }
        }

        const float leftMost   = fmaxf(rintf(minX), 0.0f);
        const float rightMost  = fminf(rintf(maxX), 255.0f);
        const float topMost    = fmaxf(rintf(minY), 0.0f);
        const float bottomMost = fminf(rintf(maxY), 255.0f);

        const float bcx = __fmul_rn(__fadd_rn(leftMost, rightMost), 0.5f);
        const float bcy = __fmul_rn(__fadd_rn(topMost, bottomMost), 0.5f);

        const float fl = floorf(bcx), ft = floorf(bcy);
        const int l  = (int)fl;
        const int t  = (int)ft;
        const int rr = (int)ceilf(bcx);
        const int bb = (int)ceilf(bcy);
        const float rx = __fsub_rn(bcx, fl);   // exact: 0.0 or 0.5
        const float ry = __fsub_rn(bcy, ft);

        const float wlt = __fmul_rn(__fsub_rn(1.0f, rx), __fsub_rn(1.0f, ry));
        const float wrt = __fmul_rn(rx, __fsub_rn(1.0f, ry));
        const float wrb = __fmul_rn(rx, ry);
        const float wlb = __fmul_rn(__fsub_rn(1.0f, rx), ry);

        const bool vl = (l  >= 0 && l  < W_);
        const bool vr = (rr >= 0 && rr < W_);
        const bool vt = (t  >= 0 && t  < H_);
        const bool vb = (bb >= 0 && bb < H_);

        const int base = b << 24;  // b * H*W*C
        const int lc = min(max(l, 0), W_ - 1),  rc = min(max(rr, 0), W_ - 1);
        const int tc = min(max(t, 0), H_ - 1),  bc = min(max(bb, 0), H_ - 1);

        // corner order must match reference sum: lt, rt, rb, lb
        soff[tid * 4 + 0] = base + (tc << 16) + (lc << 8);
        soff[tid * 4 + 1] = base + (tc << 16) + (rc << 8);
        soff[tid * 4 + 2] = base + (bc << 16) + (rc << 8);
        soff[tid * 4 + 3] = base + (bc << 16) + (lc << 8);
        swt[tid * 4 + 0] = (vt && vl) ? wlt : 0.0f;
        swt[tid * 4 + 1] = (vt && vr) ? wrt : 0.0f;
        swt[tid * 4 + 2] = (vb && vr) ? wrb : 0.0f;
        swt[tid * 4 + 3] = (vb && vl) ? wlb : 0.0f;
    }
    __syncthreads();

    // Main gather: thread = channel c; 4 coalesced (128B/warp) loads per bin.
    const int c = tid;
    const float* __restrict__ xt = g_xt;
#pragma unroll 7
    for (int bin = 0; bin < NBINS; bin++) {
        const int o0 = soff[bin * 4 + 0];
        const int o1 = soff[bin * 4 + 1];
        const int o2 = soff[bin * 4 + 2];
        const int o3 = soff[bin * 4 + 3];
        const float w0 = swt[bin * 4 + 0];
        const float w1 = swt[bin * 4 + 1];
        const float w2 = swt[bin * 4 + 2];
        const float w3 = swt[bin * 4 + 3];
        const float v0 = __ldg(xt + o0 + c);
        const float v1 = __ldg(xt + o1 + c);
        const float v2 = __ldg(xt + o2 + c);
        const float v3 = __ldg(xt + o3 + c);
        // (((lt*wlt + rt*wrt) + rb*wrb) + lb*wlb), then relu — matches ref
        const float inter = __fadd_rn(
            __fadd_rn(__fadd_rn(__fmul_rn(v0, w0), __fmul_rn(v1, w1)),
                      __fmul_rn(v2, w2)),
            __fmul_rn(v3, w3));
        sout[c * NBINS + bin] = fmaxf(inter, 0.0f);  // stride 49: no bank conflicts
    }
    __syncthreads();

    // Coalesced float4 flush: out[r][c][ph][pw] == sout[c*49 + bin]
    float4* o4 = (float4*)(out + (size_t)r * OUT_PER_ROI);
    const float4* s4 = (const float4*)sout;
    for (int i = tid; i < OUT_PER_ROI / 4; i += 256)
        o4[i] = s4[i];
}

// ---------------------------------------------------------------------------
extern "C" void kernel_launch(void* const* d_in, const int* in_sizes, int n_in,
                              void* d_out, int out_size) {
    const float* x     = (const float*)d_in[0];   // (2,256,256,256) f32
    const float* boxes = (const float*)d_in[1];   // (2,512,5) f32
    float* out = (float*)d_out;                   // (1024,256,7,7) f32

    dim3 gA(HW_ / 32, C_ / 32, B_);   // (2048, 8, 2)
    dim3 bA(32, 8);
    transpose_nchw_nhwc<<<gA, bA>>>(x);

    const int smem_bytes = NBINS * 4 * 4 * 2 + OUT_PER_ROI * 4;  // 51744
    (void)cudaFuncSetAttribute(rroi_pool_kernel,
                               cudaFuncAttributeMaxDynamicSharedMemorySize,
                               smem_bytes);
    rroi_pool_kernel<<<NROI, 256, smem_bytes>>>(boxes, out);
}

// round 3
// speedup vs baseline: 1.2398x; 1.2398x over previous
#include <cuda_runtime.h>
#include <cstdint>

// Problem constants (fixed shapes from reference setup_inputs)
#define C_   256
#define H_   256
#define W_   256
#define HW_  (H_ * W_)
#define CHW_ (C_ * H_ * W_)
#define HWC_ (H_ * W_ * C_)
#define B_   2
#define NROI 1024          // B * N = 2 * 512
#define OUTH 7
#define OUTW 7
#define NBINS 49
#define OUT_PER_ROI (C_ * NBINS)   // 12544
#define SOUT_STRIDE 260            // [49][260] floats, 4-aligned pad

// 128 MB NHWC scratch (device global — allocation-free per harness rules)
__device__ float g_xt[(size_t)B_ * HWC_];

// ---------------------------------------------------------------------------
// Kernel A: NCHW -> NHWC transpose. Per batch: 2D transpose [C=256][P=65536].
// 32x32 tiles via smem, fully coalesced reads and writes. (Near BW-bound.)
// ---------------------------------------------------------------------------
__global__ void transpose_nchw_nhwc(const float* __restrict__ x) {
    __shared__ float tile[32][33];
    const int b  = blockIdx.z;
    const int p0 = blockIdx.x * 32;   // position within H*W
    const int c0 = blockIdx.y * 32;   // channel
    const float* src = x    + (size_t)b * CHW_;
    float*       dst = g_xt + (size_t)b * HWC_;
    const int tx = threadIdx.x, ty = threadIdx.y;
#pragma unroll
    for (int j = 0; j < 32; j += 8)
        tile[ty + j][tx] = __ldg(src + (size_t)(c0 + ty + j) * HW_ + p0 + tx);
    __syncthreads();
#pragma unroll
    for (int j = 0; j < 32; j += 8)
        dst[(size_t)(p0 + ty + j) * C_ + (c0 + tx)] = tile[tx][ty + j];
}

// ---------------------------------------------------------------------------
// Kernel B: rotated ROI pool. One block per ROI.
// Thread layout: q = tid&63 -> channel quad (float4), s = tid>>6 -> bin slot;
// 4 bins in flight per iteration => 4x LDG.128 per thread = 64B MLP/iter.
// Geometry replicates reference fp32 arithmetic exactly (rel_err was 0.0).
// ---------------------------------------------------------------------------
__global__ void __launch_bounds__(256)
rroi_pool_kernel(const float* __restrict__ boxes,
                 float* __restrict__ out) {
    extern __shared__ char smem_raw[];
    int*   soff = (int*)smem_raw;                         // [49][4]
    float* swt  = (float*)(smem_raw + NBINS * 4 * 4);     // [49][4]
    float* sout = (float*)(smem_raw + NBINS * 4 * 4 * 2); // [49][260]

    const int r   = blockIdx.x;
    const int tid = threadIdx.x;

    if (tid < NBINS) {
        const float* bx = boxes + r * 5;
        const int b = r >> 9;   // batch id (N = 512 rois per batch)

        const float cx  = __fmul_rn(bx[0], 0.25f);
        const float cy  = __fmul_rn(bx[1], 0.25f);
        const float w   = __fmul_rn(bx[2], 0.25f);
        const float h   = __fmul_rn(bx[3], 0.25f);
        const float ang = __fmul_rn(bx[4], 0.017453292519943295f);

        const float Sx = __fdiv_rn(w, 7.0f);
        const float Sy = __fdiv_rn(h, 7.0f);
        const float ca = cosf(ang);
        const float sa = sinf(ang);

        const float M00 = __fmul_rn(ca, Sx);
        const float M01 = __fmul_rn(sa, Sy);
        const float M02 = __fadd_rn(
            __fadd_rn(__fmul_rn(M00, -3.5f), __fmul_rn(M01, -3.5f)), cx);
        const float M10 = __fmul_rn(-sa, Sx);
        const float M11 = __fmul_rn(ca, Sy);
        const float M12 = __fadd_rn(
            __fadd_rn(__fmul_rn(M10, -3.5f), __fmul_rn(M11, -3.5f)), cy);

        const int ph = tid / OUTW;
        const int pw = tid % OUTW;
        const float phf = (float)ph, pwf = (float)pw;

        float minX =  1e30f, maxX = -1e30f, minY = 1e30f, maxY = -1e30f;
#pragma unroll
        for (int i = 0; i < 2; i++) {
#pragma unroll
            for (int j = 0; j < 2; j++) {
                const float pc = pwf + (float)i;
                const float qc = phf + (float)j;
                const float X = __fadd_rn(
                    __fadd_rn(__fmul_rn(M00, pc), __fmul_rn(M01, qc)), M02);
                const float Y = __fadd_rn(
                    __fadd_rn(__fmul_rn(M10, pc), __fmul_rn(M11, qc)), M12);
                minX = fminf(minX, X); maxX = fmaxf(maxX, X);
                minY = fminf(minY, Y); maxY = fmaxf(maxY, Y);
            }
        }

        const float leftMost   = fmaxf(rintf(minX), 0.0f);
        const float rightMost  = fminf(rintf(maxX), 255.0f);
        const float topMost    = fmaxf(rintf(minY), 0.0f);
        const float bottomMost = fminf(rintf(maxY), 255.0f);

        const float bcx = __fmul_rn(__fadd_rn(leftMost, rightMost), 0.5f);
        const float bcy = __fmul_rn(__fadd_rn(topMost, bottomMost), 0.5f);

        const float fl = floorf(bcx), ft = floorf(bcy);
        const int l  = (int)fl;
        const int t  = (int)ft;
        const int rr = (int)ceilf(bcx);
        const int bb = (int)ceilf(bcy);
        const float rx = __fsub_rn(bcx, fl);   // exact: 0.0 or 0.5
        const float ry = __fsub_rn(bcy, ft);

        const float wlt = __fmul_rn(__fsub_rn(1.0f, rx), __fsub_rn(1.0f, ry));
        const float wrt = __fmul_rn(rx, __fsub_rn(1.0f, ry));
        const float wrb = __fmul_rn(rx, ry);
        const float wlb = __fmul_rn(__fsub_rn(1.0f, rx), ry);

        const bool vl = (l  >= 0 && l  < W_);
        const bool vr = (rr >= 0 && rr < W_);
        const bool vt = (t  >= 0 && t  < H_);
        const bool vb = (bb >= 0 && bb < H_);

        const int base = b << 24;  // b * H*W*C
        const int lc = min(max(l, 0), W_ - 1),  rc = min(max(rr, 0), W_ - 1);
        const int tc = min(max(t, 0), H_ - 1),  bc = min(max(bb, 0), H_ - 1);

        // corner order must match reference sum: lt, rt, rb, lb
        soff[tid * 4 + 0] = base + (tc << 16) + (lc << 8);
        soff[tid * 4 + 1] = base + (tc << 16) + (rc << 8);
        soff[tid * 4 + 2] = base + (bc << 16) + (rc << 8);
        soff[tid * 4 + 3] = base + (bc << 16) + (lc << 8);
        swt[tid * 4 + 0] = (vt && vl) ? wlt : 0.0f;
        swt[tid * 4 + 1] = (vt && vr) ? wrt : 0.0f;
        swt[tid * 4 + 2] = (vb && vr) ? wrb : 0.0f;
        swt[tid * 4 + 3] = (vb && vl) ? wlb : 0.0f;
    }
    __syncthreads();

    // Main gather: thread -> (bin slot s, channel quad q). 4 x LDG.128 per
    // bin; warp = 32 consecutive quads = contiguous 512B per corner.
    const int q  = tid & 63;
    const int s  = tid >> 6;
    const int c4 = q << 2;
    const float* __restrict__ xt = g_xt;

#pragma unroll 2
    for (int iter = 0; iter < 13; iter++) {
        const int bin = iter * 4 + s;
        if (bin < NBINS) {
            const int o0 = soff[bin * 4 + 0] + c4;
            const int o1 = soff[bin * 4 + 1] + c4;
            const int o2 = soff[bin * 4 + 2] + c4;
            const int o3 = soff[bin * 4 + 3] + c4;
            const float4 v0 = __ldg((const float4*)(xt + o0));
            const float4 v1 = __ldg((const float4*)(xt + o1));
            const float4 v2 = __ldg((const float4*)(xt + o2));
            const float4 v3 = __ldg((const float4*)(xt + o3));
            const float w0 = swt[bin * 4 + 0];
            const float w1 = swt[bin * 4 + 1];
            const float w2 = swt[bin * 4 + 2];
            const float w3 = swt[bin * 4 + 3];
            float4 res;
            // (((lt*wlt + rt*wrt) + rb*wrb) + lb*wlb), relu — matches ref
            res.x = fmaxf(__fadd_rn(__fadd_rn(__fadd_rn(
                        __fmul_rn(v0.x, w0), __fmul_rn(v1.x, w1)),
                        __fmul_rn(v2.x, w2)), __fmul_rn(v3.x, w3)), 0.0f);
            res.y = fmaxf(__fadd_rn(__fadd_rn(__fadd_rn(
                        __fmul_rn(v0.y, w0), __fmul_rn(v1.y, w1)),
                        __fmul_rn(v2.y, w2)), __fmul_rn(v3.y, w3)), 0.0f);
            res.z = fmaxf(__fadd_rn(__fadd_rn(__fadd_rn(
                        __fmul_rn(v0.z, w0), __fmul_rn(v1.z, w1)),
                        __fmul_rn(v2.z, w2)), __fmul_rn(v3.z, w3)), 0.0f);
            res.w = fmaxf(__fadd_rn(__fadd_rn(__fadd_rn(
                        __fmul_rn(v0.w, w0), __fmul_rn(v1.w, w1)),
                        __fmul_rn(v2.w, w2)), __fmul_rn(v3.w, w3)), 0.0f);
            *(float4*)(sout + bin * SOUT_STRIDE + c4) = res;  // STS.128, conflict-free
        }
    }
    __syncthreads();

    // Flush: out[r][c][bin] = sout[bin][c]; coalesced STG.128.
    float4* o4 = (float4*)(out + (size_t)r * OUT_PER_ROI);
    for (int i4 = tid; i4 < OUT_PER_ROI / 4; i4 += 256) {
        const int i = i4 << 2;
        int c = i / NBINS;
        int bin = i - c * NBINS;
        float4 v;
        v.x = sout[bin * SOUT_STRIDE + c];
        bin++; if (bin == NBINS) { bin = 0; c++; }
        v.y = sout[bin * SOUT_STRIDE + c];
        bin++; if (bin == NBINS) { bin = 0; c++; }
        v.z = sout[bin * SOUT_STRIDE + c];
        bin++; if (bin == NBINS) { bin = 0; c++; }
        v.w = sout[bin * SOUT_STRIDE + c];
        o4[i4] = v;
    }
}

// ---------------------------------------------------------------------------
extern "C" void kernel_launch(void* const* d_in, const int* in_sizes, int n_in,
                              void* d_out, int out_size) {
    const float* x     = (const float*)d_in[0];   // (2,256,256,256) f32
    const float* boxes = (const float*)d_in[1];   // (2,512,5) f32
    float* out = (float*)d_out;                   // (1024,256,7,7) f32

    dim3 gA(HW_ / 32, C_ / 32, B_);   // (2048, 8, 2)
    dim3 bA(32, 8);
    transpose_nchw_nhwc<<<gA, bA>>>(x);

    const int smem_bytes = NBINS * 4 * 4 * 2 + NBINS * SOUT_STRIDE * 4; // 52528
    (void)cudaFuncSetAttribute(rroi_pool_kernel,
                               cudaFuncAttributeMaxDynamicSharedMemorySize,
                               smem_bytes);
    rroi_pool_kernel<<<NROI, 256, smem_bytes>>>(boxes, out);
}